// round 5
// baseline (speedup 1.0000x reference)
#include <cuda_runtime.h>

#define NQ 9
#define HOUT 128
#define WOUT 128
#define HW 384

// Warp-autonomous fused kernel: no shared memory, no block barriers.
// Each thread = one 3x3 window. Each warp independently rebuilds the 9
// per-qubit (A,B) pairs from the 27 weights using __sincosf + shuffles,
// overlapped with the 9 in-flight window loads.
__global__ void __launch_bounds__(256) quanconv_fused(
    const float* __restrict__ in, const float* __restrict__ w,
    float* __restrict__ out) {

    const unsigned FULL = 0xFFFFFFFFu;
    const int tid  = threadIdx.x;
    const int lane = tid & 31;
    const int gid  = blockIdx.x * 256 + tid;    // 0..65535 windows
    const int wo = gid & (WOUT - 1);
    const int ho = (gid >> 7) & (HOUT - 1);
    const int b  = gid >> 14;

    // ---- issue weight load first ----
    const float M = 0.63245553203367586640f;    // sqrt(2/5) = W_MUL
    int wl = lane < 27 ? lane : 26;
    float ww = __ldg(w + wl) * M;

    // ---- issue all 9 window loads (independent, in flight together) ----
    const float* base = in + ((size_t)b * HW + ho * 3) * HW + wo * 3;
    float x[NQ];
#pragma unroll
    for (int kr = 0; kr < 3; kr++)
#pragma unroll
        for (int kc = 0; kc < 3; kc++)
            x[kr * 3 + kc] = __ldg(base + kr * HW + kc);

    // ---- per-warp setup: cheap trig + shuffle assembly (waits only on ww) ----
    float s, c;
    __sincosf(ww, &s, &c);
    // lanes 0..8 assemble A_q, B_q for q = lane
    float s0 = __shfl_sync(FULL, s, 3 * lane);
    float c0 = __shfl_sync(FULL, c, 3 * lane);
    float s1 = __shfl_sync(FULL, s, 3 * lane + 1);
    float c1 = __shfl_sync(FULL, c, 3 * lane + 1);
    float s2 = __shfl_sync(FULL, s, 3 * lane + 2);
    float c2 = __shfl_sync(FULL, c, 3 * lane + 2);
    float A = s1 * s2;
    float B = fmaf(c0, c2, -(s0 * c1 * s2));

    // ---- per-pixel: z = A*sin(pi x) + B*cos(pi x) (waits on x loads) ----
    const float PI_F = 3.14159274101257324219f;
    float z[NQ];
#pragma unroll
    for (int q = 0; q < NQ; q++) {
        float Aq = __shfl_sync(FULL, A, q);
        float Bq = __shfl_sync(FULL, B, q);
        float sp, cp;
        __sincosf(PI_F * x[q], &sp, &cp);
        z[q] = fmaf(Aq, sp, Bq * cp);
    }

    // out[0] = prod_{q=1..8} z_q ; out[j>=1] = prod_{q=0..j} z_q
    float suf = z[8];
#pragma unroll
    for (int q = 7; q >= 1; q--) suf *= z[q];

    float* obase = out + (size_t)b * NQ * HOUT * WOUT + (size_t)ho * WOUT + wo;
    obase[0] = suf;
    float p = z[0];
#pragma unroll
    for (int j = 1; j < NQ; j++) {
        p *= z[j];
        obase[(size_t)j * HOUT * WOUT] = p;
    }
}

extern "C" void kernel_launch(void* const* d_in, const int* in_sizes, int n_in,
                              void* d_out, int out_size) {
    const float* x = (const float*)d_in[0];   // (4,1,384,384) float32
    const float* w = (const float*)d_in[1];   // (27,) float32
    float* out = (float*)d_out;               // (4,9,128,128) float32

    quanconv_fused<<<65536 / 256, 256>>>(x, w, out);
}

// round 6
// speedup vs baseline: 1.0048x; 1.0048x over previous
#include <cuda_runtime.h>

#define NQ 9
#define HOUT 128
#define WOUT 128
#define HW 384
#define NWIN 65536
#define PLANE (HOUT * WOUT)

// 3 threads per 3x3 window (thread r = window row r = qubits 3r..3r+2).
// 10 windows per warp (lanes 0-29). Per-warp (A,B) rebuilt from weights with
// __sincosf + shuffles; 3-lane multiplicative prefix combine via shuffles.
__global__ void __launch_bounds__(256) quanconv_split3(
    const float* __restrict__ in, const float* __restrict__ w,
    float* __restrict__ out) {

    const unsigned FULL = 0xFFFFFFFFu;
    const int tid  = threadIdx.x;
    const int lane = tid & 31;
    const int g    = lane / 3;            // window slot in warp, 0..10
    const int r    = lane - 3 * g;        // row within window, 0..2
    const int Wid  = (blockIdx.x * 256 + tid) >> 5;   // global warp id

    int win = Wid * 10 + g;
    const bool active = (g < 10) && (win < NWIN);
    win = min(win, NWIN - 1);             // clamp for safe addressing
    const int wo = win & (WOUT - 1);
    const int ho = (win >> 7) & (HOUT - 1);
    const int b  = win >> 14;

    // ---- issue the 3 pixel loads early ----
    const float* base = in + ((size_t)b * HW + ho * 3 + r) * HW + wo * 3;
    float x0 = __ldg(base + 0);
    float x1 = __ldg(base + 1);
    float x2 = __ldg(base + 2);

    // ---- per-warp (A,B) from weights: cheap trig + shuffles ----
    const float M = 0.63245553203367586640f;          // sqrt(2/5) = W_MUL
    float ww = __ldg(w + (lane < 27 ? lane : 26)) * M;
    float s, c;
    __sincosf(ww, &s, &c);
    // lanes 0..8 assemble A_q, B_q for q = lane
    float s0 = __shfl_sync(FULL, s, 3 * lane);
    float c0 = __shfl_sync(FULL, c, 3 * lane);
    float s1 = __shfl_sync(FULL, s, 3 * lane + 1);
    float c1 = __shfl_sync(FULL, c, 3 * lane + 1);
    float s2 = __shfl_sync(FULL, s, 3 * lane + 2);
    float c2 = __shfl_sync(FULL, c, 3 * lane + 2);
    float Aq = s1 * s2;
    float Bq = fmaf(c0, c2, -(s0 * c1 * s2));
    // fetch this thread's 3 qubit constants (qubits 3r, 3r+1, 3r+2)
    float A0 = __shfl_sync(FULL, Aq, 3 * r);
    float B0 = __shfl_sync(FULL, Bq, 3 * r);
    float A1 = __shfl_sync(FULL, Aq, 3 * r + 1);
    float B1 = __shfl_sync(FULL, Bq, 3 * r + 1);
    float A2 = __shfl_sync(FULL, Aq, 3 * r + 2);
    float B2 = __shfl_sync(FULL, Bq, 3 * r + 2);

    // ---- z for 3 pixels ----
    const float PI_F = 3.14159274101257324219f;
    float sp, cp;
    __sincosf(PI_F * x0, &sp, &cp);
    float z0 = fmaf(A0, sp, B0 * cp);
    __sincosf(PI_F * x1, &sp, &cp);
    float z1 = fmaf(A1, sp, B1 * cp);
    __sincosf(PI_F * x2, &sp, &cp);
    float z2 = fmaf(A2, sp, B2 * cp);

    float l01 = z0 * z1;       // local prefix
    float L   = l01 * z2;      // full local product

    // ---- exchange group products L_r within the 3-lane group ----
    const int gbase = 3 * g;
    float L0 = __shfl_sync(FULL, L, gbase);
    float L1 = __shfl_sync(FULL, L, gbase + 1);
    float L2 = __shfl_sync(FULL, L, gbase + 2);

    // ---- outputs ----
    // out[j>=1] = z0..zj ; out[0] = z1..z8
    float e = (r == 0) ? 1.0f : ((r == 1) ? L0 : L0 * L1);
    float v0, v1, v2;
    int p0;
    if (r == 0) {
        v0 = (z1 * z2) * (L1 * L2);   // plane 0
        p0 = 0;
    } else {
        v0 = e * z0;                  // plane 3r
        p0 = 3 * r;
    }
    v1 = e * l01;                     // plane 3r+1
    v2 = e * L;                       // plane 3r+2

    if (active) {
        float* obase = out + (size_t)b * NQ * PLANE + (size_t)ho * WOUT + wo;
        obase[(size_t)p0 * PLANE]          = v0;
        obase[(size_t)(3 * r + 1) * PLANE] = v1;
        obase[(size_t)(3 * r + 2) * PLANE] = v2;
    }
}

extern "C" void kernel_launch(void* const* d_in, const int* in_sizes, int n_in,
                              void* d_out, int out_size) {
    const float* x = (const float*)d_in[0];   // (4,1,384,384) float32
    const float* w = (const float*)d_in[1];   // (27,) float32
    float* out = (float*)d_out;               // (4,9,128,128) float32

    // 65536 windows, 10 per warp -> 6554 warps -> 820 blocks of 8 warps
    int nwarps = (NWIN + 9) / 10;
    int nblocks = (nwarps + 7) / 8;
    quanconv_split3<<<nblocks, 256>>>(x, w, out);
}